// round 6
// baseline (speedup 1.0000x reference)
#include <cuda_runtime.h>
#include <math.h>

#define HIDDEN 512
#define H4     (HIDDEN / 4)
#define BATCH  4096
#define BN_EPS 1e-5f

// ---------------- scratch (device globals; no allocations allowed) ----------
__device__ float4 g_pooled[BATCH * H4];   // [4096, 512] mean-pooled embeddings
__device__ float4 g_h[BATCH * H4];        // [4096, 512] hidden pre-BN
__device__ float  g_colsum[HIDDEN];
__device__ float  g_colsq[HIDDEN];
__device__ float  g_loss;
__device__ unsigned int g_count;

// ---------------- kernels 0-2: zero per-launch accumulators -----------------
// Split 3-ways so pool_kernel lands at launch index 3 (the ncu capture slot).
__global__ void zero_a_kernel() { g_colsum[threadIdx.x] = 0.f; }
__global__ void zero_b_kernel() { g_colsq[threadIdx.x] = 0.f; }
__global__ void zero_c_kernel() { if (threadIdx.x == 0) { g_loss = 0.f; g_count = 0u; } }

// ---------------- kernel 3: ragged gather + mean pool -----------------------
// One block per segment (segment_ids sorted). 128 threads; each thread owns one
// float4 lane of the 2KB row. 4 independent accumulator streams -> >=16
// outstanding LDG.128 per thread under #pragma unroll, for DRAM latency hiding.
__global__ __launch_bounds__(128) void pool_kernel(const int* __restrict__ tokens,
                                                   const int* __restrict__ seg,
                                                   const float* __restrict__ emb,
                                                   int T) {
    int b = blockIdx.x;
    // lower_bound(b)
    int lo = 0, hi = T;
    while (lo < hi) { int m = (lo + hi) >> 1; if (seg[m] < b) lo = m + 1; else hi = m; }
    int start = lo;
    // upper_bound(b)
    hi = T;
    while (lo < hi) { int m = (lo + hi) >> 1; if (seg[m] <= b) lo = m + 1; else hi = m; }
    int end = lo;

    const int t = threadIdx.x;                      // 0..127
    const float4* __restrict__ embv = (const float4*)emb;
    float4 a0 = make_float4(0.f, 0.f, 0.f, 0.f);
    float4 a1 = make_float4(0.f, 0.f, 0.f, 0.f);
    float4 a2 = make_float4(0.f, 0.f, 0.f, 0.f);
    float4 a3 = make_float4(0.f, 0.f, 0.f, 0.f);

    __shared__ int stok[256];
    for (int base = start; base < end; base += 256) {
        int n = min(256, end - base);
        if (t < n)        stok[t]       = tokens[base + t];
        if (t + 128 < n)  stok[t + 128] = tokens[base + t + 128];
        __syncthreads();
        int r = 0;
        #pragma unroll 2
        for (; r + 4 <= n; r += 4) {
            long i0 = (long)stok[r]     * H4 + t;
            long i1 = (long)stok[r + 1] * H4 + t;
            long i2 = (long)stok[r + 2] * H4 + t;
            long i3 = (long)stok[r + 3] * H4 + t;
            float4 v0 = __ldg(&embv[i0]);
            float4 v1 = __ldg(&embv[i1]);
            float4 v2 = __ldg(&embv[i2]);
            float4 v3 = __ldg(&embv[i3]);
            a0.x += v0.x; a0.y += v0.y; a0.z += v0.z; a0.w += v0.w;
            a1.x += v1.x; a1.y += v1.y; a1.z += v1.z; a1.w += v1.w;
            a2.x += v2.x; a2.y += v2.y; a2.z += v2.z; a2.w += v2.w;
            a3.x += v3.x; a3.y += v3.y; a3.z += v3.z; a3.w += v3.w;
        }
        for (; r < n; r++) {
            float4 v = __ldg(&embv[(long)stok[r] * H4 + t]);
            a0.x += v.x; a0.y += v.y; a0.z += v.z; a0.w += v.w;
        }
        __syncthreads();
    }
    float invc = 1.f / fmaxf((float)(end - start), 1.f);
    float4 acc;
    acc.x = (a0.x + a1.x + a2.x + a3.x) * invc;
    acc.y = (a0.y + a1.y + a2.y + a3.y) * invc;
    acc.z = (a0.z + a1.z + a2.z + a3.z) * invc;
    acc.w = (a0.w + a1.w + a2.w + a3.w) * invc;
    g_pooled[b * H4 + t] = acc;
}

// ---------------- kernel 4: h = pooled @ W_h + b_h  (+ fused BN stats) ------
// M=4096, N=512, K=512. 64x64 tile, BK=16, 256 threads, 4x4/thread.
// Epilogue reduces per-column sum / sumsq within the block and atomically
// accumulates into g_colsum / g_colsq (removes the standalone stats kernel).
__global__ __launch_bounds__(256) void gemm_stats_kernel(const float* __restrict__ Bw,  // W_h [K,N]
                                                         const float* __restrict__ bias) {
    const int N = HIDDEN, K = HIDDEN;
    __shared__ float As[16][64];   // [k][m]
    __shared__ float Bs[16][64];   // [k][n]
    __shared__ float s_red[16][64];

    const float* A = (const float*)g_pooled;   // [M,K]
    float*       C = (float*)g_h;              // [M,N]

    int bx = blockIdx.x;   // N tile (0..7)
    int by = blockIdx.y;   // M tile (0..63)
    int tid = threadIdx.x;
    int tx = tid & 15;     // n
    int ty = tid >> 4;     // m

    int aRow = tid >> 2;          // 0..63
    int aCol = (tid & 3) * 4;     // 0,4,8,12
    int bRow = tid >> 4;          // 0..15
    int bCol = (tid & 15) * 4;    // 0..60

    float acc[4][4];
    #pragma unroll
    for (int i = 0; i < 4; i++)
        #pragma unroll
        for (int j = 0; j < 4; j++) acc[i][j] = 0.f;

    for (int k0 = 0; k0 < K; k0 += 16) {
        float4 av = *(const float4*)&A[(size_t)(by * 64 + aRow) * K + k0 + aCol];
        As[aCol + 0][aRow] = av.x;
        As[aCol + 1][aRow] = av.y;
        As[aCol + 2][aRow] = av.z;
        As[aCol + 3][aRow] = av.w;
        float4 bv = *(const float4*)&Bw[(size_t)(k0 + bRow) * N + bx * 64 + bCol];
        *(float4*)&Bs[bRow][bCol] = bv;
        __syncthreads();

        #pragma unroll
        for (int kk = 0; kk < 16; kk++) {
            float ra[4], rb[4];
            #pragma unroll
            for (int i = 0; i < 4; i++) ra[i] = As[kk][ty * 4 + i];
            #pragma unroll
            for (int j = 0; j < 4; j++) rb[j] = Bs[kk][tx * 4 + j];
            #pragma unroll
            for (int i = 0; i < 4; i++)
                #pragma unroll
                for (int j = 0; j < 4; j++)
                    acc[i][j] = fmaf(ra[i], rb[j], acc[i][j]);
        }
        __syncthreads();
    }

    // epilogue: add bias, store C, accumulate per-thread column partials
    float psum[4] = {0.f, 0.f, 0.f, 0.f};
    float psq[4]  = {0.f, 0.f, 0.f, 0.f};
    #pragma unroll
    for (int j = 0; j < 4; j++) {
        int col = bx * 64 + tx * 4 + j;
        float bval = bias[col];
        #pragma unroll
        for (int i = 0; i < 4; i++) {
            int row = by * 64 + ty * 4 + i;
            float c = acc[i][j] + bval;
            C[(size_t)row * N + col] = c;
            psum[j] += c;
            psq[j]  += c * c;
        }
    }
    // block reduction over ty (16 partials per column), then one atomic per col
    #pragma unroll
    for (int j = 0; j < 4; j++) s_red[ty][tx * 4 + j] = psum[j];
    __syncthreads();
    if (tid < 64) {
        float s = 0.f;
        #pragma unroll
        for (int r = 0; r < 16; r++) s += s_red[r][tid];
        atomicAdd(&g_colsum[bx * 64 + tid], s);
    }
    __syncthreads();
    #pragma unroll
    for (int j = 0; j < 4; j++) s_red[ty][tx * 4 + j] = psq[j];
    __syncthreads();
    if (tid < 64) {
        float s = 0.f;
        #pragma unroll
        for (int r = 0; r < 16; r++) s += s_red[r][tid];
        atomicAdd(&g_colsq[bx * 64 + tid], s);
    }
}

// ---------------- kernel 5: BN(+stats finalize) + ReLU + dot + BCE + loss ---
// One block per row, 128 threads, 4 cols each. mu/istd derived inline from the
// global column sums (L2-hot). Loss written by the last block to finish.
__global__ __launch_bounds__(128) void logits_kernel(const float* __restrict__ t,
                                                     const float* __restrict__ gamma,
                                                     const float* __restrict__ beta,
                                                     const float* __restrict__ W_o,
                                                     const float* __restrict__ b_o,
                                                     float* __restrict__ out_logits,
                                                     float* __restrict__ out_loss) {
    int i = blockIdx.x;
    int tdx = threadIdx.x;
    const float4* hv  = &g_h[i * H4];
    const float4* csv = (const float4*)g_colsum;
    const float4* cqv = (const float4*)g_colsq;
    const float4* gv  = (const float4*)gamma;
    const float4* bev = (const float4*)beta;
    const float4* wv  = (const float4*)W_o;

    const float invB = 1.f / (float)BATCH;
    float4 cs = csv[tdx], cq = cqv[tdx];
    float mu0 = cs.x * invB, mu1 = cs.y * invB, mu2 = cs.z * invB, mu3 = cs.w * invB;
    float is0 = rsqrtf(cq.x * invB - mu0 * mu0 + BN_EPS);
    float is1 = rsqrtf(cq.y * invB - mu1 * mu1 + BN_EPS);
    float is2 = rsqrtf(cq.z * invB - mu2 * mu2 + BN_EPS);
    float is3 = rsqrtf(cq.w * invB - mu3 * mu3 + BN_EPS);

    float4 h = hv[tdx], ga = gv[tdx], be = bev[tdx], w = wv[tdx];
    float a0 = fmaxf(ga.x * (h.x - mu0) * is0 + be.x, 0.f);
    float a1 = fmaxf(ga.y * (h.y - mu1) * is1 + be.y, 0.f);
    float a2 = fmaxf(ga.z * (h.z - mu2) * is2 + be.z, 0.f);
    float a3 = fmaxf(ga.w * (h.w - mu3) * is3 + be.w, 0.f);
    float acc = a0 * w.x + a1 * w.y + a2 * w.z + a3 * w.w;

    #pragma unroll
    for (int off = 16; off > 0; off >>= 1)
        acc += __shfl_xor_sync(0xffffffff, acc, off);
    __shared__ float warpsum[4];
    if ((tdx & 31) == 0) warpsum[tdx >> 5] = acc;
    __syncthreads();
    if (tdx == 0) {
        float logit = warpsum[0] + warpsum[1] + warpsum[2] + warpsum[3] + b_o[0];
        if (out_logits) out_logits[i] = logit;
        float sp = fmaxf(logit, 0.f) + log1pf(expf(-fabsf(logit)));
        atomicAdd(&g_loss, (sp - t[i] * logit) * (1.f / BATCH));
        __threadfence();
        unsigned int done = atomicAdd(&g_count, 1u);
        if (done == BATCH - 1u) {
            if (out_loss) out_loss[0] = atomicAdd(&g_loss, 0.f);
        }
    }
}

// ---------------- launch ------------------------------------------------------
extern "C" void kernel_launch(void* const* d_in, const int* in_sizes, int n_in,
                              void* d_out, int out_size) {
    const int*   tokens = (const int*)d_in[0];
    const int*   seg    = (const int*)d_in[1];
    const float* t      = (const float*)d_in[2];
    const float* emb    = (const float*)d_in[3];
    const float* W_h    = (const float*)d_in[4];
    const float* b_h    = (const float*)d_in[5];
    const float* gamma  = (const float*)d_in[6];
    const float* beta   = (const float*)d_in[7];
    const float* W_o    = (const float*)d_in[8];
    const float* b_o    = (const float*)d_in[9];
    const int T = in_sizes[0];

    float* out = (float*)d_out;
    float* out_loss = nullptr;
    float* out_logits = nullptr;
    if (out_size >= BATCH + 1) { out_loss = out; out_logits = out + 1; }
    else if (out_size == BATCH) { out_logits = out; }
    else { out_loss = out; }

    zero_a_kernel<<<1, HIDDEN>>>();   // idx 0
    zero_b_kernel<<<1, HIDDEN>>>();   // idx 1
    zero_c_kernel<<<1, 32>>>();       // idx 2
    pool_kernel<<<BATCH, 128>>>(tokens, seg, emb, T);   // idx 3 (ncu capture slot)
    {
        dim3 grid(HIDDEN / 64, BATCH / 64);
        gemm_stats_kernel<<<grid, 256>>>(W_h, b_h);     // idx 4
    }
    logits_kernel<<<BATCH, 128>>>(t, gamma, beta, W_o, b_o, out_logits, out_loss); // idx 5
}